// round 16
// baseline (speedup 1.0000x reference)
#include <cuda_runtime.h>
#include <cuda_fp16.h>
#include <stdint.h>

// Problem constants
#define BB     2
#define SQL    2048
#define SKVL   2048
#define DMODEL 1024
#define NH     16
#define HDIM   64
#define MQ     (BB*SQL)    // 4096
#define MKV    (BB*SKVL)   // 4096

// ---------------- scratch (device globals; no runtime allocation) ----------------
__device__ __half g_xq_h [MQ*DMODEL];
__device__ __half g_xkv_h[MKV*DMODEL];
__device__ __half g_wq_h [DMODEL*DMODEL];
__device__ __half g_wk_h [DMODEL*DMODEL];
__device__ __half g_wv_h [DMODEL*DMODEL];
__device__ __half g_wo_h [DMODEL*DMODEL];
__device__ __half g_qh   [MQ*DMODEL];   // [B,H,SQ,HD], pre-scaled by 1/8, rope applied
__device__ __half g_kh   [MKV*DMODEL];  // [B,H,SKV,HD], rope applied
__device__ __half g_vh   [MKV*DMODEL];  // [B,H,SKV,HD]
__device__ __half g_ctx_h[MQ*DMODEL];   // [B,SQ,D]

// ---------------- cp.async / mma / ldmatrix helpers ----------------
__device__ __forceinline__ void cp16(void* smem, const void* gmem) {
    uint32_t s = (uint32_t)__cvta_generic_to_shared(smem);
    asm volatile("cp.async.cg.shared.global [%0], [%1], 16;\n" :: "r"(s), "l"(gmem));
}
__device__ __forceinline__ void cp_commit() { asm volatile("cp.async.commit_group;\n"); }
template<int N> __device__ __forceinline__ void cp_wait() {
    asm volatile("cp.async.wait_group %0;\n" :: "n"(N));
}
__device__ __forceinline__ void ldsm_x4(uint32_t* r, uint32_t addr) {
    asm volatile("ldmatrix.sync.aligned.m8n8.x4.shared.b16 {%0,%1,%2,%3}, [%4];"
        : "=r"(r[0]), "=r"(r[1]), "=r"(r[2]), "=r"(r[3]) : "r"(addr));
}
__device__ __forceinline__ void ldsm_x4_t(uint32_t* r, uint32_t addr) {
    asm volatile("ldmatrix.sync.aligned.m8n8.x4.trans.shared.b16 {%0,%1,%2,%3}, [%4];"
        : "=r"(r[0]), "=r"(r[1]), "=r"(r[2]), "=r"(r[3]) : "r"(addr));
}
__device__ __forceinline__ void mma16816(float* c, const uint32_t* a, uint32_t b0, uint32_t b1) {
    asm volatile("mma.sync.aligned.m16n8k16.row.col.f32.f16.f16.f32 "
        "{%0,%1,%2,%3}, {%4,%5,%6,%7}, {%8,%9}, {%0,%1,%2,%3};"
        : "+f"(c[0]), "+f"(c[1]), "+f"(c[2]), "+f"(c[3])
        : "r"(a[0]), "r"(a[1]), "r"(a[2]), "r"(a[3]), "r"(b0), "r"(b1));
}
__device__ __forceinline__ uint32_t h2u(float a, float b) {
    __half2 h = __floats2half2_rn(a, b);
    return *reinterpret_cast<uint32_t*>(&h);
}

// ---------------- fused fp32->fp16 convert (all 6 tensors, one launch) ----------------
__global__ void cvt_all(const float* __restrict__ xq, const float* __restrict__ xkv,
                        const float* __restrict__ wq, const float* __restrict__ wk,
                        const float* __restrict__ wv, const float* __restrict__ wo,
                        __half* oxq, __half* oxkv, __half* owq, __half* owk,
                        __half* owv, __half* owo) {
    int i = blockIdx.x * blockDim.x + threadIdx.x;   // float4 index, total 3M
    const float* src; __half* dst; int off;
    if (i < 1048576)      { src = xq;  dst = oxq;  off = i; }
    else if (i < 2097152) { src = xkv; dst = oxkv; off = i - 1048576; }
    else {
        int j = i - 2097152;
        int w = j >> 18;
        off = j & 262143;
        switch (w) {
            case 0: src = wq; dst = owq; break;
            case 1: src = wk; dst = owk; break;
            case 2: src = wv; dst = owv; break;
            default: src = wo; dst = owo; break;
        }
    }
    float4 v = reinterpret_cast<const float4*>(src)[off];
    reinterpret_cast<__half2*>(dst)[2*off]   = __floats2half2_rn(v.x, v.y);
    reinterpret_cast<__half2*>(dst)[2*off+1] = __floats2half2_rn(v.z, v.w);
}

// ---------------- raw-mma GEMM mainloop: 8 warps, 32x64 warp tile, 3-stage cp.async ----------------
// Batched-LDSM schedule: all fragment loads for a kk-step issue back-to-back,
// then the 16 MMAs run dependence-free.
#define GBM 128
#define GBN 128
#define GBK 32
#define GLD 40
#define GST_HALFS (GBM * GLD)
#define GSTAGE_BYTES (2 * GST_HALFS * 2)
#define GEMM_SMEM (3 * GSTAGE_BYTES)       // 61440 B
#define GTHREADS 256

__device__ __forceinline__ void gemm_mainloop_raw(
    const __half* __restrict__ A, const __half* __restrict__ Bm,
    char* dsm, int bm, int bn, float (&acc)[2][8][4]) {

    const int K = DMODEL;
    int tid  = threadIdx.x;
    int lane = tid & 31;
    int warp = tid >> 5;
    int wm   = warp & 3;
    int wn   = warp >> 2;

    #pragma unroll
    for (int i = 0; i < 2; i++)
        #pragma unroll
        for (int j = 0; j < 8; j++)
            #pragma unroll
            for (int e = 0; e < 4; e++) acc[i][j][e] = 0.0f;

    uint32_t dsm_u = (uint32_t)__cvta_generic_to_shared(dsm);

    uint32_t offA = (((uint32_t)(lane & 15)) * GLD + (uint32_t)(lane >> 4) * 8) * 2;
    uint32_t offB = ((((uint32_t)(lane & 7) + ((lane >> 4) & 1) * 8)) * GLD
                     + (uint32_t)((lane >> 3) & 1) * 8) * 2;

    int lrow = tid >> 2;
    int lcol = (tid & 3) * 8;

    auto load_stage = [&](int st, int kt) {
        int k0 = kt * GBK;
        __half* As = (__half*)(dsm + st * GSTAGE_BYTES);
        __half* Bs = As + GST_HALFS;
        #pragma unroll
        for (int p = 0; p < 2; p++) {
            int r = lrow + p * 64;
            cp16(As + r * GLD + lcol, A  + (size_t)(bm + r) * K + k0 + lcol);
            cp16(Bs + r * GLD + lcol, Bm + (size_t)(bn + r) * K + k0 + lcol);
        }
    };

    load_stage(0, 0); cp_commit();
    load_stage(1, 1); cp_commit();

    const int NK = K / GBK; // 32
    for (int kt = 0; kt < NK; kt++) {
        int st = kt % 3;
        if (kt == NK - 1) cp_wait<0>(); else cp_wait<1>();
        __syncthreads();
        if (kt + 2 < NK) { load_stage((kt + 2) % 3, kt + 2); cp_commit(); }

        uint32_t asb = dsm_u + st * GSTAGE_BYTES;
        uint32_t bsb = asb + GST_HALFS * 2;

        #pragma unroll
        for (int kk = 0; kk < GBK; kk += 16) {
            // ---- batch ALL fragment loads first ----
            uint32_t a[2][4];
            uint32_t b[4][4];
            #pragma unroll
            for (int i = 0; i < 2; i++)
                ldsm_x4(a[i], asb + ((uint32_t)(wm * 32 + i * 16) * GLD + kk) * 2 + offA);
            #pragma unroll
            for (int jt = 0; jt < 4; jt++)
                ldsm_x4(b[jt], bsb + ((uint32_t)(wn * 64 + jt * 16) * GLD + kk) * 2 + offB);
            // ---- then 16 dependence-free MMAs ----
            #pragma unroll
            for (int jt = 0; jt < 4; jt++)
                #pragma unroll
                for (int i = 0; i < 2; i++) {
                    mma16816(acc[i][jt * 2],     a[i], b[jt][0], b[jt][1]);
                    mma16816(acc[i][jt * 2 + 1], a[i], b[jt][2], b[jt][3]);
                }
        }
    }
}

// ---------------- combined Q/K/V projection kernel (grid.z selects) ----------------
__global__ __launch_bounds__(GTHREADS, 2)
void gemm_proj(const __half* __restrict__ xq, const __half* __restrict__ xkv,
               const __half* __restrict__ wq, const __half* __restrict__ wk,
               const __half* __restrict__ wv,
               const float* __restrict__ bq, const float* __restrict__ bk,
               const float* __restrict__ bv,
               __half* __restrict__ qh, __half* __restrict__ kh, __half* __restrict__ vh) {
    extern __shared__ char dsm[];
    int z = blockIdx.z;
    const __half* A  = (z == 0) ? xq : xkv;
    const __half* Bm = (z == 0) ? wq : (z == 1) ? wk : wv;
    const float* bias = (z == 0) ? bq : (z == 1) ? bk : bv;
    __half* Oh = (z == 0) ? qh : (z == 1) ? kh : vh;
    float scale = (z == 0) ? 0.125f : 1.0f;
    bool do_rope = (z < 2);

    int bm = blockIdx.y * GBM;
    int bn = blockIdx.x * GBN;

    float acc[2][8][4];
    gemm_mainloop_raw(A, Bm, dsm, bm, bn, acc);

    int lane = threadIdx.x & 31;
    int warp = threadIdx.x >> 5;
    int wm = warp & 3, wn = warp >> 2;
    int g = lane >> 2, tig = lane & 3;

    #pragma unroll
    for (int i = 0; i < 2; i++) {
        int r0 = bm + wm * 32 + i * 16 + g;
        #pragma unroll
        for (int j = 0; j < 8; j++) {
            int c = bn + wn * 64 + j * 8 + tig * 2;
            const float* x = acc[i][j];
            int head = c >> 6;
            int hd   = c & 63;
            float be = bias[c], bo2 = bias[c + 1];
            #pragma unroll
            for (int p = 0; p < 2; p++) {
                int row = r0 + p * 8;
                float xe = x[p * 2]     + be;
                float xo = x[p * 2 + 1] + bo2;
                int s  = row & (SQL - 1);
                int bi = row >> 11;
                float re, ro;
                if (do_rope) {
                    int pr = hd >> 1;
                    float freq = expf(-(float)pr * (9.210340371976184f / 32.0f));
                    float ang  = (float)s * freq;
                    float cs = cosf(ang), sn = sinf(ang);
                    re = (xe * cs - xo * sn) * scale;
                    ro = (xe * sn + xo * cs) * scale;
                } else {
                    re = xe; ro = xo;
                }
                *(__half2*)(Oh + ((size_t)(bi * NH + head) * SQL + s) * HDIM + hd) =
                    __floats2half2_rn(re, ro);
            }
        }
    }
}

// ---------------- output projection kernel (f32 out + bias) ----------------
__global__ __launch_bounds__(GTHREADS, 2)
void gemm_out(const __half* __restrict__ A, const __half* __restrict__ Bm,
              const float* __restrict__ bias, float* __restrict__ C) {
    extern __shared__ char dsm[];
    int bm = blockIdx.y * GBM;
    int bn = blockIdx.x * GBN;

    float acc[2][8][4];
    gemm_mainloop_raw(A, Bm, dsm, bm, bn, acc);

    int lane = threadIdx.x & 31;
    int warp = threadIdx.x >> 5;
    int wm = warp & 3, wn = warp >> 2;
    int g = lane >> 2, tig = lane & 3;
    const int N = DMODEL;

    #pragma unroll
    for (int i = 0; i < 2; i++) {
        int r0 = bm + wm * 32 + i * 16 + g;
        #pragma unroll
        for (int j = 0; j < 8; j++) {
            int c = bn + wn * 64 + j * 8 + tig * 2;
            const float* x = acc[i][j];
            float be = bias[c], bo2 = bias[c + 1];
            float2 v0 = { x[0] + be, x[1] + bo2 };
            float2 v1 = { x[2] + be, x[3] + bo2 };
            *(float2*)(C + (size_t)r0 * N + c)       = v0;
            *(float2*)(C + (size_t)(r0 + 8) * N + c) = v1;
        }
    }
}

// ---------------- flash attention v5: raw mma, register P, batched LDSM ----------------
#define FQT  128
#define FKT  64
#define FLD  72
#define KVS  (FKT * FLD)

#define FSMEM_BYTES ((FQT*FLD + 6*KVS) * 2)   // 73728 B

__global__ __launch_bounds__(256, 2)
void flash4(const __half* __restrict__ Q, const __half* __restrict__ K,
            const __half* __restrict__ V, __half* __restrict__ CTX) {
    extern __shared__ __half fsh[];
    __half* Qs = fsh;
    __half* Ks = Qs + FQT * FLD;
    __half* Vs = Ks + 3 * KVS;

    int tid  = threadIdx.x;
    int lane = tid & 31;
    int warp = tid >> 5;
    int g    = lane >> 2;
    int tig  = lane & 3;
    int b    = blockIdx.z;
    int h    = blockIdx.y;
    int q0   = blockIdx.x * FQT;
    int wrow = warp * 16;

    const __half* qptr  = Q + ((size_t)(b * NH + h) * SQL + q0) * HDIM;
    const __half* kbase = K + (size_t)(b * NH + h) * SKVL * HDIM;
    const __half* vbase = V + (size_t)(b * NH + h) * SKVL * HDIM;

    for (int i = tid; i < FQT * 8; i += 256) {
        int r = i >> 3, c = (i & 7) * 8;
        *(float4*)(Qs + r * FLD + c) = *(const float4*)(qptr + r * HDIM + c);
    }

    auto copy_kv = [&](int st, int kt) {
        #pragma unroll
        for (int p = 0; p < 4; p++) {
            int i = tid + p * 256;
            int r = (i >> 3) & 63, c = (i & 7) * 8;
            if (i < 512)
                cp16(Ks + st * KVS + r * FLD + c, kbase + (size_t)(kt + r) * HDIM + c);
            else
                cp16(Vs + st * KVS + r * FLD + c, vbase + (size_t)(kt + r) * HDIM + c);
        }
    };

    copy_kv(0, 0); cp_commit();
    copy_kv(1, FKT); cp_commit();
    __syncthreads();

    uint32_t qs_u  = (uint32_t)__cvta_generic_to_shared(Qs);
    uint32_t ks_u  = (uint32_t)__cvta_generic_to_shared(Ks);
    uint32_t vs_u  = (uint32_t)__cvta_generic_to_shared(Vs);
    uint32_t offQV = (((uint32_t)(lane & 15)) * FLD + (uint32_t)(lane >> 4) * 8) * 2;
    uint32_t offK  = ((((uint32_t)(lane & 7) + ((lane >> 4) & 1) * 8)) * FLD
                      + (uint32_t)((lane >> 3) & 1) * 8) * 2;

    uint32_t qa[4][4];
    #pragma unroll
    for (int kk = 0; kk < 4; kk++)
        ldsm_x4(qa[kk], qs_u + ((uint32_t)(wrow) * FLD + kk * 16) * 2 + offQV);

    float m0 = -1e30f, m1 = -1e30f, l0 = 0.0f, l1 = 0.0f;
    float O[8][4];
    #pragma unroll
    for (int j = 0; j < 8; j++)
        #pragma unroll
        for (int e = 0; e < 4; e++) O[j][e] = 0.0f;

    const int NT = SKVL / FKT;  // 32
    for (int t = 0; t < NT; t++) {
        int st = t % 3;
        if (t == NT - 1) cp_wait<0>(); else cp_wait<1>();
        __syncthreads();
        if (t + 2 < NT) { copy_kv((t + 2) % 3, (t + 2) * FKT); cp_commit(); }

        uint32_t kst = ks_u + (uint32_t)(st * KVS) * 2;
        uint32_t vst = vs_u + (uint32_t)(st * KVS) * 2;

        float S[8][4];
        #pragma unroll
        for (int j = 0; j < 8; j++)
            #pragma unroll
            for (int e = 0; e < 4; e++) S[j][e] = 0.0f;

        // ---- S = Q K^T: per kk, batch 4 K-fragment loads, then 8 MMAs ----
        #pragma unroll
        for (int kk = 0; kk < 4; kk++) {
            uint32_t kb[4][4];
            #pragma unroll
            for (int jp = 0; jp < 4; jp++)
                ldsm_x4(kb[jp], kst + ((uint32_t)(jp * 16) * FLD + kk * 16) * 2 + offK);
            #pragma unroll
            for (int jp = 0; jp < 4; jp++) {
                mma16816(S[2*jp],   qa[kk], kb[jp][0], kb[jp][1]);
                mma16816(S[2*jp+1], qa[kk], kb[jp][2], kb[jp][3]);
            }
        }

        float mx0 = -1e30f, mx1 = -1e30f;
        #pragma unroll
        for (int j = 0; j < 8; j++) {
            mx0 = fmaxf(mx0, fmaxf(S[j][0], S[j][1]));
            mx1 = fmaxf(mx1, fmaxf(S[j][2], S[j][3]));
        }
        mx0 = fmaxf(mx0, __shfl_xor_sync(0xffffffffu, mx0, 1));
        mx0 = fmaxf(mx0, __shfl_xor_sync(0xffffffffu, mx0, 2));
        mx1 = fmaxf(mx1, __shfl_xor_sync(0xffffffffu, mx1, 1));
        mx1 = fmaxf(mx1, __shfl_xor_sync(0xffffffffu, mx1, 2));

        float mn0 = fmaxf(m0, mx0), mn1 = fmaxf(m1, mx1);
        float a0  = __expf(m0 - mn0), a1 = __expf(m1 - mn1);

        uint32_t PA[4][4];
        float s0 = 0.0f, s1 = 0.0f;
        #pragma unroll
        for (int j = 0; j < 8; j++) {
            float e0 = __expf(S[j][0] - mn0), e1 = __expf(S[j][1] - mn0);
            float e2 = __expf(S[j][2] - mn1), e3 = __expf(S[j][3] - mn1);
            s0 += e0 + e1;  s1 += e2 + e3;
            int kk = j >> 1, hf = (j & 1) * 2;
            PA[kk][hf]     = h2u(e0, e1);
            PA[kk][hf + 1] = h2u(e2, e3);
        }
        s0 += __shfl_xor_sync(0xffffffffu, s0, 1);
        s0 += __shfl_xor_sync(0xffffffffu, s0, 2);
        s1 += __shfl_xor_sync(0xffffffffu, s1, 1);
        s1 += __shfl_xor_sync(0xffffffffu, s1, 2);

        l0 = l0 * a0 + s0;  l1 = l1 * a1 + s1;
        m0 = mn0;           m1 = mn1;

        #pragma unroll
        for (int j = 0; j < 8; j++) {
            O[j][0] *= a0; O[j][1] *= a0;
            O[j][2] *= a1; O[j][3] *= a1;
        }

        // ---- O += P V: per kk, batch 4 V-fragment loads, then 8 MMAs ----
        #pragma unroll
        for (int kk = 0; kk < 4; kk++) {
            uint32_t vb[4][4];
            #pragma unroll
            for (int jp = 0; jp < 4; jp++)
                ldsm_x4_t(vb[jp], vst + ((uint32_t)(kk * 16) * FLD + jp * 16) * 2 + offQV);
            #pragma unroll
            for (int jp = 0; jp < 4; jp++) {
                mma16816(O[2*jp],   PA[kk], vb[jp][0], vb[jp][1]);
                mma16816(O[2*jp+1], PA[kk], vb[jp][2], vb[jp][3]);
            }
        }
    }

    float il0 = 1.0f / l0, il1 = 1.0f / l1;
    int r = q0 + wrow + g;
    __half* o0 = CTX + (size_t)(b * SQL + r) * DMODEL + h * HDIM + tig * 2;
    __half* o1 = o0 + 8 * DMODEL;
    #pragma unroll
    for (int j = 0; j < 8; j++) {
        __half2 v0 = __floats2half2_rn(O[j][0] * il0, O[j][1] * il0);
        __half2 v1 = __floats2half2_rn(O[j][2] * il1, O[j][3] * il1);
        *(__half2*)(o0 + j * 8) = v0;
        *(__half2*)(o1 + j * 8) = v1;
    }
}

// ---------------- host ----------------
extern "C" void kernel_launch(void* const* d_in, const int* in_sizes, int n_in,
                              void* d_out, int out_size) {
    const float* x_q  = (const float*)d_in[0];
    const float* x_kv = (const float*)d_in[1];
    const float* wq   = (const float*)d_in[2];
    const float* bq   = (const float*)d_in[3];
    const float* wk   = (const float*)d_in[4];
    const float* bk   = (const float*)d_in[5];
    const float* wv   = (const float*)d_in[6];
    const float* bv   = (const float*)d_in[7];
    const float* wo   = (const float*)d_in[8];
    const float* bo   = (const float*)d_in[9];
    float* out = (float*)d_out;

    void *p_xq, *p_xkv, *p_wq, *p_wk, *p_wv, *p_wo;
    void *p_qh, *p_kh, *p_vh, *p_ctx;
    cudaGetSymbolAddress(&p_xq,  g_xq_h);
    cudaGetSymbolAddress(&p_xkv, g_xkv_h);
    cudaGetSymbolAddress(&p_wq,  g_wq_h);
    cudaGetSymbolAddress(&p_wk,  g_wk_h);
    cudaGetSymbolAddress(&p_wv,  g_wv_h);
    cudaGetSymbolAddress(&p_wo,  g_wo_h);
    cudaGetSymbolAddress(&p_qh,  g_qh);
    cudaGetSymbolAddress(&p_kh,  g_kh);
    cudaGetSymbolAddress(&p_vh,  g_vh);
    cudaGetSymbolAddress(&p_ctx, g_ctx_h);

    cudaFuncSetAttribute(flash4,    cudaFuncAttributeMaxDynamicSharedMemorySize, FSMEM_BYTES);
    cudaFuncSetAttribute(gemm_proj, cudaFuncAttributeMaxDynamicSharedMemorySize, GEMM_SMEM);
    cudaFuncSetAttribute(gemm_out,  cudaFuncAttributeMaxDynamicSharedMemorySize, GEMM_SMEM);

    // one fused convert launch: 3M float4 chunks
    cvt_all<<<12288, 256>>>(x_q, x_kv, wq, wk, wv, wo,
                            (__half*)p_xq, (__half*)p_xkv, (__half*)p_wq,
                            (__half*)p_wk, (__half*)p_wv, (__half*)p_wo);

    // combined Q/K/V projections (bias + rope + relayout fused), one launch
    dim3 pgrid(DMODEL / GBN, MQ / GBM, 3);   // (8, 32, 3)
    gemm_proj<<<pgrid, GTHREADS, GEMM_SMEM>>>(
        (const __half*)p_xq, (const __half*)p_xkv,
        (const __half*)p_wq, (const __half*)p_wk, (const __half*)p_wv,
        bq, bk, bv,
        (__half*)p_qh, (__half*)p_kh, (__half*)p_vh);

    // flash attention
    dim3 fgrid(SQL / FQT, NH, BB);
    flash4<<<fgrid, 256, FSMEM_BYTES>>>((const __half*)p_qh, (const __half*)p_kh,
                                        (const __half*)p_vh, (__half*)p_ctx);

    // output projection (+bias fused)
    dim3 ogrid(DMODEL / GBN, MQ / GBM);
    gemm_out<<<ogrid, GTHREADS, GEMM_SMEM>>>((const __half*)p_ctx, (const __half*)p_wo, bo, out);
}